// round 7
// baseline (speedup 1.0000x reference)
#include <cuda_runtime.h>
#include <math.h>

// BucketingBBoxCoder decode, GB300 sm_103a. Round 7:
// R6 (ncu 42.4us, DRAM 78.8%) had a 5.54-wave grid -> ~8% tail-wave waste.
// Persistent grid-stride kernel: grid = 148 SMs x 5 blocks = 740 (matches the
// (256,5) occupancy target), each thread loops ~5.5 proposals. No tail wave,
// and cross-iteration load overlap raises effective MLP.

#define TOTAL (8 * 131072)       // 1,048,576 proposals
#define SCALE_F 3.0f
#define INV_NB (1.0f / 14.0f)
#define W_CLAMP 1332.0f
#define H_CLAMP 799.0f

#define NBLOCKS 740              // 148 SMs * 5 resident blocks
#define TPB 256

__global__ __launch_bounds__(TPB, 5)
void bucketing_bbox_kernel(const float4* __restrict__ proposals,   // [TOTAL] float4
                           const float4* __restrict__ cls4,        // [TOTAL*7] float4
                           const float*  __restrict__ off,         // [TOTAL*28] float
                           float4* __restrict__ out_bbox,          // [TOTAL] float4
                           float* __restrict__ out_conf)           // [TOTAL]
{
    const int stride = NBLOCKS * TPB;

    for (int p = blockIdx.x * TPB + threadIdx.x; p < TOTAL; p += stride) {

        // ---- front-batched streaming loads: 1 proposal + 7 cls float4 ----
        const float4 pr = __ldcs(&proposals[p]);

        const size_t base = (size_t)p * 7;
        float c[28];
#pragma unroll
        for (int k = 0; k < 7; k++) {
            float4 v = __ldcs(&cls4[base + k]);
            c[4*k+0] = v.x; c[4*k+1] = v.y; c[4*k+2] = v.z; c[4*k+3] = v.w;
        }

        // ---- geometry ----
        const float cx = (pr.x + pr.z) * 0.5f;
        const float cy = (pr.y + pr.w) * 0.5f;
        const float pw = (pr.z - pr.x) * SCALE_F;
        const float ph = (pr.w - pr.y) * SCALE_F;
        const float px1 = cx - 0.5f * pw;
        const float px2 = cx + 0.5f * pw;
        const float py1 = cy - 0.5f * ph;
        const float py2 = cy + 0.5f * ph;
        const float bw = pw * INV_NB;
        const float bh = ph * INV_NB;

        const float edge_base[4] = { px1, px2, py1, py2 };
        const float edge_sign[4] = { 1.0f, -1.0f, 1.0f, -1.0f };
        const float edge_bsz [4] = { bw, bw, bh, bh };
        const float edge_hi  [4] = { W_CLAMP, W_CLAMP, H_CLAMP, H_CLAMP };

        // ---- per-edge top-2 + softmax-top values ----
        int   i1v[4];
        float conf_sum = 0.0f;

#pragma unroll
        for (int e = 0; e < 4; e++) {
            float m1 = c[e*7 + 0]; int i1 = 0;
            float m2 = -INFINITY;  int i2 = 0;
#pragma unroll
            for (int s = 1; s < 7; s++) {
                const float v = c[e*7 + s];
                if (v > m1)      { m2 = m1; i2 = i1; m1 = v; i1 = s; }
                else if (v > m2) { m2 = v; i2 = s; }
            }

            // s==i2 term of the softmax sum IS exp(m2-m1): capture, don't recompute
            float sum = 0.0f;
            float e2  = 0.0f;
#pragma unroll
            for (int s = 0; s < 7; s++) {
                const float ev = __expf(c[e*7 + s] - m1);
                sum += ev;
                e2 = (s == i2) ? ev : e2;
            }
            const float t1 = 1.0f / sum;
            const float t2 = e2 * t1;

            conf_sum += t1 + t2 * (fabsf((float)(i1 - i2)) - 1.0f);
            i1v[e] = i1;
        }

        // ---- gather exactly the 4 selected offsets ----
        const float* offp = off + (size_t)p * 28;
        const float o0 = __ldcs(offp +  0 + i1v[0]);
        const float o1 = __ldcs(offp +  7 + i1v[1]);
        const float o2 = __ldcs(offp + 14 + i1v[2]);
        const float o3 = __ldcs(offp + 21 + i1v[3]);
        const float ov[4] = { o0, o1, o2, o3 };

        float coord[4];
#pragma unroll
        for (int e = 0; e < 4; e++) {
            float cval = edge_base[e]
                       + edge_sign[e] * (0.5f + (float)i1v[e]) * edge_bsz[e]
                       - ov[e] * edge_bsz[e];
            coord[e] = fminf(fmaxf(cval, 0.0f), edge_hi[e]);
        }

        float4 bb;
        bb.x = coord[0];
        bb.y = coord[2];
        bb.z = coord[1];
        bb.w = coord[3];
        __stcs(&out_bbox[p], bb);
        __stcs(&out_conf[p], conf_sum * 0.25f);
    }
}

extern "C" void kernel_launch(void* const* d_in, const int* in_sizes, int n_in,
                              void* d_out, int out_size)
{
    const float4* proposals = (const float4*)d_in[0];
    const float4* cls4      = (const float4*)d_in[1];
    const float*  off       = (const float*)d_in[2];

    float4* out_bbox = (float4*)d_out;
    float*  out_conf = (float*)d_out + (size_t)TOTAL * 4;

    bucketing_bbox_kernel<<<NBLOCKS, TPB>>>(proposals, cls4, off,
                                            out_bbox, out_conf);
}

// round 8
// speedup vs baseline: 1.0515x; 1.0515x over previous
#include <cuda_runtime.h>
#include <math.h>

// BucketingBBoxCoder decode, GB300 sm_103a. Round 8:
// = R6 (best: ncu 42.4us, DRAM 78.8%) exactly, reverting R7's persistent loop,
// + L2 prefetch of the per-thread 112B offset region issued with the front
//   load batch, so the end-of-chain offset gathers hit L2 instead of DRAM.

#define TOTAL (8 * 131072)       // 1,048,576 proposals
#define SCALE_F 3.0f
#define INV_NB (1.0f / 14.0f)
#define W_CLAMP 1332.0f
#define H_CLAMP 799.0f

__global__ __launch_bounds__(256, 5)
void bucketing_bbox_kernel(const float4* __restrict__ proposals,   // [TOTAL] float4
                           const float4* __restrict__ cls4,        // [TOTAL*7] float4
                           const float*  __restrict__ off,         // [TOTAL*28] float
                           float4* __restrict__ out_bbox,          // [TOTAL] float4
                           float* __restrict__ out_conf)           // [TOTAL]
{
    const int p = blockIdx.x * blockDim.x + threadIdx.x;
    if (p >= TOTAL) return;

    // ---- front-batched streaming loads: 1 proposal + 7 cls float4 (MLP=8) ----
    const float4 pr = __ldcs(&proposals[p]);

    const float* offp = off + (size_t)p * 28;
    // fire-and-forget: pull this thread's 112B offset region into L2 now,
    // so the dependent gathers below are L2 hits, not DRAM misses.
    asm volatile("prefetch.global.L2 [%0];"      :: "l"(offp)      );
    asm volatile("prefetch.global.L2 [%0];"      :: "l"(offp + 8)  );
    asm volatile("prefetch.global.L2 [%0];"      :: "l"(offp + 16) );
    asm volatile("prefetch.global.L2 [%0];"      :: "l"(offp + 24) );

    const size_t base = (size_t)p * 7;
    float c[28];
#pragma unroll
    for (int k = 0; k < 7; k++) {
        float4 v = __ldcs(&cls4[base + k]);
        c[4*k+0] = v.x; c[4*k+1] = v.y; c[4*k+2] = v.z; c[4*k+3] = v.w;
    }

    // ---- geometry ----
    const float cx = (pr.x + pr.z) * 0.5f;
    const float cy = (pr.y + pr.w) * 0.5f;
    const float pw = (pr.z - pr.x) * SCALE_F;
    const float ph = (pr.w - pr.y) * SCALE_F;
    const float px1 = cx - 0.5f * pw;
    const float px2 = cx + 0.5f * pw;
    const float py1 = cy - 0.5f * ph;
    const float py2 = cy + 0.5f * ph;
    const float bw = pw * INV_NB;
    const float bh = ph * INV_NB;

    const float edge_base[4] = { px1, px2, py1, py2 };
    const float edge_sign[4] = { 1.0f, -1.0f, 1.0f, -1.0f };
    const float edge_bsz [4] = { bw, bw, bh, bh };
    const float edge_hi  [4] = { W_CLAMP, W_CLAMP, H_CLAMP, H_CLAMP };

    // ---- per-edge top-2 + softmax-top values ----
    int   i1v[4];
    float conf_sum = 0.0f;

#pragma unroll
    for (int e = 0; e < 4; e++) {
        float m1 = c[e*7 + 0]; int i1 = 0;
        float m2 = -INFINITY;  int i2 = 0;
#pragma unroll
        for (int s = 1; s < 7; s++) {
            const float v = c[e*7 + s];
            if (v > m1)      { m2 = m1; i2 = i1; m1 = v; i1 = s; }
            else if (v > m2) { m2 = v; i2 = s; }
        }

        // the s==i2 term of the softmax sum IS exp(m2-m1): capture, don't recompute
        float sum = 0.0f;
        float e2  = 0.0f;
#pragma unroll
        for (int s = 0; s < 7; s++) {
            const float ev = __expf(c[e*7 + s] - m1);
            sum += ev;
            e2 = (s == i2) ? ev : e2;
        }
        const float t1 = 1.0f / sum;
        const float t2 = e2 * t1;

        conf_sum += t1 + t2 * (fabsf((float)(i1 - i2)) - 1.0f);
        i1v[e] = i1;
    }

    // ---- gather exactly the 4 selected offsets (L2-resident by now) ----
    const float o0 = __ldcs(offp +  0 + i1v[0]);
    const float o1 = __ldcs(offp +  7 + i1v[1]);
    const float o2 = __ldcs(offp + 14 + i1v[2]);
    const float o3 = __ldcs(offp + 21 + i1v[3]);
    const float ov[4] = { o0, o1, o2, o3 };

    float coord[4];
#pragma unroll
    for (int e = 0; e < 4; e++) {
        float cval = edge_base[e]
                   + edge_sign[e] * (0.5f + (float)i1v[e]) * edge_bsz[e]
                   - ov[e] * edge_bsz[e];
        coord[e] = fminf(fmaxf(cval, 0.0f), edge_hi[e]);
    }

    float4 bb;
    bb.x = coord[0];
    bb.y = coord[2];
    bb.z = coord[1];
    bb.w = coord[3];
    __stcs(&out_bbox[p], bb);
    __stcs(&out_conf[p], conf_sum * 0.25f);
}

extern "C" void kernel_launch(void* const* d_in, const int* in_sizes, int n_in,
                              void* d_out, int out_size)
{
    const float4* proposals = (const float4*)d_in[0];
    const float4* cls4      = (const float4*)d_in[1];
    const float*  off       = (const float*)d_in[2];

    float4* out_bbox = (float4*)d_out;
    float*  out_conf = (float*)d_out + (size_t)TOTAL * 4;

    const int threads = 256;
    const int blocks  = (TOTAL + threads - 1) / threads;
    bucketing_bbox_kernel<<<blocks, threads>>>(proposals, cls4, off,
                                               out_bbox, out_conf);
}

// round 9
// speedup vs baseline: 1.2116x; 1.1522x over previous
#include <cuda_runtime.h>
#include <math.h>

// BucketingBBoxCoder decode, GB300 sm_103a. Round 9 = Round 6 verbatim (best).
// R6 is pinned on the memory roofline: 264MB moved at ~6.24TB/s = 42.4us ncu.
// Post-R6 experiments all regressed:
//   R7 persistent grid: loop fences broke cross-iteration load batching.
//   R8 L2 prefetch: doubled LTS traffic for offsets, throttled the stream.
// Structure: 1 thread/proposal; front-batched __ldcs loads (proposal + 7 cls
// float4, MLP=8); register-only top-2 with e2 captured inside the softmax sum;
// 4 scalar end-of-chain offset gathers; __stcs outputs. (256,5), 46 regs.

#define TOTAL (8 * 131072)       // 1,048,576 proposals
#define SCALE_F 3.0f
#define INV_NB (1.0f / 14.0f)
#define W_CLAMP 1332.0f
#define H_CLAMP 799.0f

__global__ __launch_bounds__(256, 5)
void bucketing_bbox_kernel(const float4* __restrict__ proposals,   // [TOTAL] float4
                           const float4* __restrict__ cls4,        // [TOTAL*7] float4
                           const float*  __restrict__ off,         // [TOTAL*28] float
                           float4* __restrict__ out_bbox,          // [TOTAL] float4
                           float* __restrict__ out_conf)           // [TOTAL]
{
    const int p = blockIdx.x * blockDim.x + threadIdx.x;
    if (p >= TOTAL) return;

    // ---- front-batched streaming loads: 1 proposal + 7 cls float4 (MLP=8) ----
    const float4 pr = __ldcs(&proposals[p]);

    const size_t base = (size_t)p * 7;
    float c[28];
#pragma unroll
    for (int k = 0; k < 7; k++) {
        float4 v = __ldcs(&cls4[base + k]);
        c[4*k+0] = v.x; c[4*k+1] = v.y; c[4*k+2] = v.z; c[4*k+3] = v.w;
    }

    // ---- geometry ----
    const float cx = (pr.x + pr.z) * 0.5f;
    const float cy = (pr.y + pr.w) * 0.5f;
    const float pw = (pr.z - pr.x) * SCALE_F;
    const float ph = (pr.w - pr.y) * SCALE_F;
    const float px1 = cx - 0.5f * pw;
    const float px2 = cx + 0.5f * pw;
    const float py1 = cy - 0.5f * ph;
    const float py2 = cy + 0.5f * ph;
    const float bw = pw * INV_NB;
    const float bh = ph * INV_NB;

    const float edge_base[4] = { px1, px2, py1, py2 };
    const float edge_sign[4] = { 1.0f, -1.0f, 1.0f, -1.0f };
    const float edge_bsz [4] = { bw, bw, bh, bh };
    const float edge_hi  [4] = { W_CLAMP, W_CLAMP, H_CLAMP, H_CLAMP };

    // ---- per-edge top-2 + softmax-top values ----
    int   i1v[4];
    float conf_sum = 0.0f;

#pragma unroll
    for (int e = 0; e < 4; e++) {
        float m1 = c[e*7 + 0]; int i1 = 0;
        float m2 = -INFINITY;  int i2 = 0;
#pragma unroll
        for (int s = 1; s < 7; s++) {
            const float v = c[e*7 + s];
            if (v > m1)      { m2 = m1; i2 = i1; m1 = v; i1 = s; }
            else if (v > m2) { m2 = v; i2 = s; }
        }

        // the s==i2 term of the softmax sum IS exp(m2-m1): capture, don't recompute
        float sum = 0.0f;
        float e2  = 0.0f;
#pragma unroll
        for (int s = 0; s < 7; s++) {
            const float ev = __expf(c[e*7 + s] - m1);
            sum += ev;
            e2 = (s == i2) ? ev : e2;
        }
        const float t1 = 1.0f / sum;
        const float t2 = e2 * t1;

        conf_sum += t1 + t2 * (fabsf((float)(i1 - i2)) - 1.0f);
        i1v[e] = i1;
    }

    // ---- gather exactly the 4 selected offsets (independent streaming LDGs) ----
    const float* offp = off + (size_t)p * 28;
    const float o0 = __ldcs(offp +  0 + i1v[0]);
    const float o1 = __ldcs(offp +  7 + i1v[1]);
    const float o2 = __ldcs(offp + 14 + i1v[2]);
    const float o3 = __ldcs(offp + 21 + i1v[3]);
    const float ov[4] = { o0, o1, o2, o3 };

    float coord[4];
#pragma unroll
    for (int e = 0; e < 4; e++) {
        float cval = edge_base[e]
                   + edge_sign[e] * (0.5f + (float)i1v[e]) * edge_bsz[e]
                   - ov[e] * edge_bsz[e];
        coord[e] = fminf(fmaxf(cval, 0.0f), edge_hi[e]);
    }

    float4 bb;
    bb.x = coord[0];
    bb.y = coord[2];
    bb.z = coord[1];
    bb.w = coord[3];
    __stcs(&out_bbox[p], bb);
    __stcs(&out_conf[p], conf_sum * 0.25f);
}

extern "C" void kernel_launch(void* const* d_in, const int* in_sizes, int n_in,
                              void* d_out, int out_size)
{
    const float4* proposals = (const float4*)d_in[0];
    const float4* cls4      = (const float4*)d_in[1];
    const float*  off       = (const float*)d_in[2];

    float4* out_bbox = (float4*)d_out;
    float*  out_conf = (float*)d_out + (size_t)TOTAL * 4;

    const int threads = 256;
    const int blocks  = (TOTAL + threads - 1) / threads;
    bucketing_bbox_kernel<<<blocks, threads>>>(proposals, cls4, off,
                                               out_bbox, out_conf);
}